// round 15
// baseline (speedup 1.0000x reference)
#include <cuda_runtime.h>
#include <cuda_bf16.h>
#include <cstdint>

// Problem constants
#define BATCH 4
#define SEQT  2048
#define DMODEL 512
#define NHEAD 8
#define HD    64
#define THREE_D (3 * DMODEL)
#define MROWS (BATCH * SEQT)        // 8192

// Arch-feature dispatch: tcgen05/bulk-async only on *a targets.
#if !defined(__CUDA_ARCH__)
#  define TC_PATH 1
#elif defined(__CUDA_ARCH_HAS_FEATURE__) && \
      (__CUDA_ARCH_HAS_FEATURE__(SM103_ALL) || __CUDA_ARCH_HAS_FEATURE__(SM100_ALL))
#  define TC_PATH 1
#else
#  define TC_PATH 0
#endif

// ---------------------------------------------------------------------------
// MERGED tiled+swizzled bf16 hi/lo operand layout (SW64), TR=128:
//   tile t = (rblk * (K/32) + kblk) occupies 16 KB at t*16384:
//     [hi half: 8 KB][lo half: 8 KB]
//   within a half: row r, col c (bf16): bo = r*64 + c*2, bo ^= ((bo>>3)&0x30)
// ---------------------------------------------------------------------------

// Scratch (no cudaMalloc allowed)
__device__ float g_qkv[(size_t)MROWS * THREE_D];   // 48 MB fp32
__device__ alignas(128) __nv_bfloat16 g_x  [(size_t)MROWS   * DMODEL * 2];
__device__ alignas(128) __nv_bfloat16 g_wi [(size_t)THREE_D * DMODEL * 2];
__device__ alignas(128) __nv_bfloat16 g_wo [(size_t)DMODEL  * DMODEL * 2];
__device__ alignas(128) __nv_bfloat16 g_att[(size_t)MROWS   * DMODEL * 2];

// ===========================================================================
// Common helpers
// ===========================================================================
__device__ __forceinline__ uint32_t pack_bf16x2(__nv_bfloat16 a, __nv_bfloat16 b) {
    return (uint32_t)__bfloat16_as_ushort(a) |
           ((uint32_t)__bfloat16_as_ushort(b) << 16);
}

__device__ __forceinline__ void split_hilo(float v, __nv_bfloat16& h, __nv_bfloat16& l) {
    h = __float2bfloat16(v);
    l = __float2bfloat16(v - __bfloat162float(h));
}

__device__ __forceinline__ uint32_t sw64(uint32_t bo) {
    return bo ^ ((bo >> 3) & 0x30);
}

// merged-tiled element load (fallback path only), TR=128; half=0 hi, 1 lo
__device__ __forceinline__ float ld_tiled(
    const __nv_bfloat16* base, int row, int col, int Kdim, int half)
{
    int kblk = col >> 5, cin = col & 31;
    int rblk = row >> 7, rin = row & 127;
    size_t tile = ((size_t)(rblk * (Kdim >> 5) + kblk)) << 14;
    uint32_t bo = sw64((uint32_t)(rin * 64 + cin * 2)) + half * 8192;
    return __bfloat162float(*(const __nv_bfloat16*)((const char*)base + tile + bo));
}

// ===========================================================================
// fp32 row-major -> MERGED tiled+swizzled bf16 hi/lo (TR=128). 8 elems/thread.
// ===========================================================================
__global__ __launch_bounds__(256) void cvt_tiled_kernel(
    const float* __restrict__ src,
    __nv_bfloat16* __restrict__ dst, int R, int Kdim)
{
    int i = blockIdx.x * blockDim.x + threadIdx.x;
    int n8 = (R * Kdim) >> 3;
    if (i >= n8) return;
    const int K8 = Kdim >> 3;
    int row = i / K8;
    int c8  = i - row * K8;

    float4 v0 = __ldg((const float4*)src + i * 2);
    float4 v1 = __ldg((const float4*)src + i * 2 + 1);

    __nv_bfloat16 h0,l0,h1,l1,h2,l2,h3,l3,h4,l4,h5,l5,h6,l6,h7,l7;
    split_hilo(v0.x,h0,l0); split_hilo(v0.y,h1,l1);
    split_hilo(v0.z,h2,l2); split_hilo(v0.w,h3,l3);
    split_hilo(v1.x,h4,l4); split_hilo(v1.y,h5,l5);
    split_hilo(v1.z,h6,l6); split_hilo(v1.w,h7,l7);
    uint4 hi, lo;
    hi.x = pack_bf16x2(h0,h1); hi.y = pack_bf16x2(h2,h3);
    hi.z = pack_bf16x2(h4,h5); hi.w = pack_bf16x2(h6,h7);
    lo.x = pack_bf16x2(l0,l1); lo.y = pack_bf16x2(l2,l3);
    lo.z = pack_bf16x2(l4,l5); lo.w = pack_bf16x2(l6,l7);

    int kblk = c8 >> 2, cc = c8 & 3;
    int rblk = row >> 7, rin = row & 127;
    size_t tile = ((size_t)(rblk * (Kdim >> 5) + kblk)) << 14;
    uint32_t bo = sw64((uint32_t)(rin * 64 + cc * 16));
    *(uint4*)((char*)dst + tile + bo)        = hi;
    *(uint4*)((char*)dst + tile + 8192 + bo) = lo;
}

// ===========================================================================
// tcgen05 + bulk-async PTX helpers (feature-gated)
// ===========================================================================
#if TC_PATH
__device__ __forceinline__ uint32_t smem_u32(const void* p) {
    uint32_t a;
    asm("{ .reg .u64 t; cvta.to.shared.u64 t, %1; cvt.u32.u64 %0, t; }"
        : "=r"(a) : "l"(p));
    return a;
}

#define TCGEN05_ALLOC(smem_result_addr, nCols) \
    asm volatile( \
        "tcgen05.alloc.cta_group::1.sync.aligned.shared::cta.b32 [%0], %1;" \
        :: "r"((uint32_t)(smem_result_addr)), "r"((uint32_t)(nCols)) : "memory")

#define TCGEN05_DEALLOC(tmem_addr, nCols) \
    asm volatile( \
        "tcgen05.dealloc.cta_group::1.sync.aligned.b32 %0, %1;" \
        :: "r"(tmem_addr), "r"((uint32_t)(nCols)))

#define TCGEN05_RELINQUISH_ALLOC_PERMIT() \
    asm volatile("tcgen05.relinquish_alloc_permit.cta_group::1.sync.aligned;")

#define TCGEN05_COMMIT(mbar_smem_addr) \
    asm volatile( \
        "tcgen05.commit.cta_group::1.mbarrier::arrive::one.shared::cluster.b64 [%0];" \
        :: "r"((uint32_t)(mbar_smem_addr)) : "memory")

#define TCGEN05_FENCE_AFTER() \
    asm volatile("tcgen05.fence::after_thread_sync;" ::: "memory")

#define TCGEN05_WAIT_LD() \
    asm volatile("tcgen05.wait::ld.sync.aligned;" ::: "memory")

#define MBARRIER_INIT(mbar_smem_addr, count) \
    asm volatile( \
        "mbarrier.init.shared.b64 [%0], %1;" \
        :: "r"((uint32_t)(mbar_smem_addr)), "r"((uint32_t)(count)) : "memory")

#define MBARRIER_EXPECT_TX(mbar_smem_addr, tx_bytes) \
    asm volatile( \
        "mbarrier.arrive.expect_tx.shared.b64 _, [%0], %1;" \
        :: "r"((uint32_t)(mbar_smem_addr)), "r"((uint32_t)(tx_bytes)) : "memory")

#define MBARRIER_WAIT_PARITY(mbar_smem_addr, phase_parity) do { \
    uint32_t _mbar = (uint32_t)(mbar_smem_addr); \
    uint32_t _parity = (uint32_t)(phase_parity); \
    uint32_t _done; \
    asm volatile( \
        "{\n\t.reg .pred p;\n\t" \
        "mbarrier.try_wait.parity.acquire.cta.shared::cta.b64 p, [%1], %2;\n\t" \
        "selp.b32 %0, 1, 0, p;\n\t}" \
        : "=r"(_done) : "r"(_mbar), "r"(_parity) : "memory"); \
    if (!_done) { \
        asm volatile( \
            "{\n\t.reg .pred P1;\n\t" \
            "WAIT_LOOP_%=:\n\t" \
            "mbarrier.try_wait.parity.acquire.cta.shared::cta.b64 P1, [%0], %1, 0x989680;\n\t" \
            "@P1 bra.uni WAIT_DONE_%=;\n\t" \
            "bra.uni WAIT_LOOP_%=;\n\t" \
            "WAIT_DONE_%=:\n\t}" \
            :: "r"(_mbar), "r"(_parity) : "memory"); \
    } \
} while(0)

#define BULK_G2S(dst_smem, src_gmem, nbytes, mbar) \
    asm volatile( \
        "cp.async.bulk.shared::cluster.global.mbarrier::complete_tx::bytes " \
        "[%0], [%1], %2, [%3];" \
        :: "r"((uint32_t)(dst_smem)), "l"(src_gmem), "r"((uint32_t)(nbytes)), \
           "r"((uint32_t)(mbar)) : "memory")

#define TCGEN05_LD_32X32B_X32(r, tmem_addr) \
    asm volatile( \
        "tcgen05.ld.sync.aligned.32x32b.x32.b32 " \
        "{%0, %1, %2, %3, %4, %5, %6, %7, " \
        " %8, %9, %10, %11, %12, %13, %14, %15, " \
        " %16, %17, %18, %19, %20, %21, %22, %23, " \
        " %24, %25, %26, %27, %28, %29, %30, %31}, [%32];" \
        : "=r"((r)[0]),  "=r"((r)[1]),  "=r"((r)[2]),  "=r"((r)[3]), \
          "=r"((r)[4]),  "=r"((r)[5]),  "=r"((r)[6]),  "=r"((r)[7]), \
          "=r"((r)[8]),  "=r"((r)[9]),  "=r"((r)[10]), "=r"((r)[11]), \
          "=r"((r)[12]), "=r"((r)[13]), "=r"((r)[14]), "=r"((r)[15]), \
          "=r"((r)[16]), "=r"((r)[17]), "=r"((r)[18]), "=r"((r)[19]), \
          "=r"((r)[20]), "=r"((r)[21]), "=r"((r)[22]), "=r"((r)[23]), \
          "=r"((r)[24]), "=r"((r)[25]), "=r"((r)[26]), "=r"((r)[27]), \
          "=r"((r)[28]), "=r"((r)[29]), "=r"((r)[30]), "=r"((r)[31]) \
        : "r"(tmem_addr))

// SW64 descriptor: layout=4, version=1, SBO=32 (512B atom), LBO=1 (16B)
static constexpr uint64_t SMEM_DESC_BASE_SW64 =
    (uint64_t(4)  << 61) | (uint64_t(1) << 46) |
    (uint64_t(32) << 32) | (uint64_t(1) << 16);
#define MAKE_SMEM_DESC_SW64(base_addr) \
    (SMEM_DESC_BASE_SW64 | ((uint64_t)((base_addr) >> 4) & 0x3FFF))

__device__ __forceinline__ void mma_f16_ss_cg1(
    uint32_t d_tmem, uint64_t a_desc, uint64_t b_desc,
    uint32_t idesc, uint32_t enable)
{
    asm volatile(
        "{\n\t.reg .pred p;\n\t"
        "setp.ne.u32 p, %4, 0;\n\t"
        "tcgen05.mma.cta_group::1.kind::f16 [%0], %1, %2, %3, "
        "{%5, %5, %5, %5}, p;\n\t}"
        :: "r"(d_tmem), "l"(a_desc), "l"(b_desc), "r"(idesc),
           "r"(enable), "r"(0u)
        : "memory");
}

#define GEMM_IDESC ((1u<<4)|(1u<<7)|(1u<<10)|(16u<<17)|(8u<<24))  // M128 N128 bf16 f32acc
#endif // TC_PATH

// ---- out-proj kernel: NPIPE=2 x 32KB = 66KB -> 3 CTAs/SM ----
#define STAGE128 32768
#define NP128 2
#define SMEM128 (1024 + NP128 * STAGE128)

// ---- QKV kernel (M128 x N256): NPIPE=2 x 48KB = 97KB -> 2 CTAs/SM ----
#define STAGE256 49152
#define NP256 2
#define SMEM256 (1024 + NP256 * STAGE256)

// ===========================================================================
// GEMM 128x128 (merged hi/lo, TR=128). Warp-specialized, NPIPE=2, 3 CTAs/SM.
// Used for the output projection.
// ===========================================================================
__global__ __launch_bounds__(128, 3) void tc_gemm_128(
    const __nv_bfloat16* __restrict__ A, const __nv_bfloat16* __restrict__ B,
    const float* __restrict__ bias, float* __restrict__ C,
    int M, int N, int K)
{
    extern __shared__ char smem[];
    const int tid = threadIdx.x;
    const int bm = blockIdx.y * 128;
    const int bn = blockIdx.x * 128;

#if TC_PATH
    const uint32_t smem_base = smem_u32(smem);
    const int wid  = tid >> 5;
    const int lane = tid & 31;

#define FULLB(b) (smem_base + 8  + 16 * (b))
#define EMPTB(b) (smem_base + 64 + 16 * (b))

    if (wid == 0) {
        TCGEN05_ALLOC(smem_base, 128);
        TCGEN05_RELINQUISH_ALLOC_PERMIT();
        if (lane == 0) {
#pragma unroll
            for (int b = 0; b < NP128; b++) {
                MBARRIER_INIT(FULLB(b), 1);
                MBARRIER_INIT(EMPTB(b), 1);
            }
        }
    }
    __syncthreads();
    uint32_t tmem;
    asm volatile("ld.shared.b32 %0, [%1];" : "=r"(tmem) : "r"(smem_base));

    const int nstage = K >> 5;
    const int nkblk  = K >> 5;

    if (tid == 32) {
        const size_t arow = (size_t)(bm >> 7) * nkblk;
        const size_t brow = (size_t)(bn >> 7) * nkblk;
        int eph[NP128] = {0, 0};
        int buf = 0;
        for (int s = 0; s < nstage; s++) {
            const uint32_t OFF = smem_base + 1024 + buf * STAGE128;
            if (s >= NP128) { MBARRIER_WAIT_PARITY(EMPTB(buf), eph[buf]); eph[buf] ^= 1; }
            MBARRIER_EXPECT_TX(FULLB(buf), STAGE128);
            BULK_G2S(OFF,         (const char*)A + ((arow + s) << 14), 16384, FULLB(buf));
            BULK_G2S(OFF + 16384, (const char*)B + ((brow + s) << 14), 16384, FULLB(buf));
            if (++buf == NP128) buf = 0;
        }
#pragma unroll
        for (int b = 0; b < NP128; b++)
            MBARRIER_WAIT_PARITY(EMPTB(b), eph[b]);
    }
    if (tid == 0) {
        int fph[NP128] = {0, 0};
        int buf = 0;
        for (int s = 0; s < nstage; s++) {
            const uint32_t OFF = smem_base + 1024 + buf * STAGE128;

            MBARRIER_WAIT_PARITY(FULLB(buf), fph[buf]); fph[buf] ^= 1;

            uint64_t ah = MAKE_SMEM_DESC_SW64(OFF);
            uint64_t al = MAKE_SMEM_DESC_SW64(OFF + 8192);
            uint64_t bh = MAKE_SMEM_DESC_SW64(OFF + 16384);
            uint64_t bl = MAKE_SMEM_DESC_SW64(OFF + 24576);
#pragma unroll
            for (int kk = 0; kk < 2; kk++) {
                uint32_t en = (s > 0 || kk > 0) ? 1u : 0u;
                mma_f16_ss_cg1(tmem, ah + kk*2, bh + kk*2, GEMM_IDESC, en);
                mma_f16_ss_cg1(tmem, ah + kk*2, bl + kk*2, GEMM_IDESC, 1u);
                mma_f16_ss_cg1(tmem, al + kk*2, bh + kk*2, GEMM_IDESC, 1u);
            }
            TCGEN05_COMMIT(EMPTB(buf));
            if (++buf == NP128) buf = 0;
        }
    }
    __syncthreads();
    TCGEN05_FENCE_AFTER();

    {
        const int rowo = bm + wid * 32 + lane;
#pragma unroll
        for (int cb = 0; cb < 128; cb += 32) {
            uint32_t d[32];
            TCGEN05_LD_32X32B_X32(d, tmem + cb);
            TCGEN05_WAIT_LD();
            float* crow = C + (size_t)rowo * N + bn + cb;
#pragma unroll
            for (int g = 0; g < 8; g++) {
                float4 bb = __ldg((const float4*)(bias + bn + cb + g * 4));
                float4 o;
                o.x = __uint_as_float(d[g*4+0]) + bb.x;
                o.y = __uint_as_float(d[g*4+1]) + bb.y;
                o.z = __uint_as_float(d[g*4+2]) + bb.z;
                o.w = __uint_as_float(d[g*4+3]) + bb.w;
                *(float4*)(crow + g * 4) = o;
            }
        }
    }
    __syncthreads();
    if (wid == 0) {
        TCGEN05_DEALLOC(tmem, 128);
    }
#undef FULLB
#undef EMPTB

#else
    // FFMA fallback 128x128 (merged tiled loads)
    float* As = (float*)smem;
    float* Bs = (float*)(smem + 4096);

    const int trow = tid >> 4;
    const int tcol = tid & 15;
    float acc[16][8];
#pragma unroll
    for (int i = 0; i < 16; i++)
#pragma unroll
        for (int j = 0; j < 8; j++) acc[i][j] = 0.0f;

    for (int k0 = 0; k0 < K; k0 += 8) {
        for (int idx = tid; idx < 8 * 128; idx += 128) {
            int kk = idx >> 7, rr = idx & 127;
            As[kk * 128 + rr] =
                ld_tiled(A, bm + rr, k0 + kk, K, 0) +
                ld_tiled(A, bm + rr, k0 + kk, K, 1);
            Bs[kk * 128 + rr] =
                ld_tiled(B, bn + rr, k0 + kk, K, 0) +
                ld_tiled(B, bn + rr, k0 + kk, K, 1);
        }
        __syncthreads();
#pragma unroll
        for (int kk = 0; kk < 8; kk++) {
            float a[16], b[8];
#pragma unroll
            for (int e = 0; e < 16; e++) a[e] = As[kk * 128 + trow * 16 + e];
#pragma unroll
            for (int e = 0; e < 8; e++)  b[e] = Bs[kk * 128 + tcol * 8 + e];
#pragma unroll
            for (int i = 0; i < 16; i++)
#pragma unroll
                for (int j = 0; j < 8; j++)
                    acc[i][j] += a[i] * b[j];
        }
        __syncthreads();
    }
    const int cn = bn + tcol * 8;
#pragma unroll
    for (int i = 0; i < 16; i++) {
        const int row = bm + trow * 16 + i;
#pragma unroll
        for (int j = 0; j < 8; j++)
            C[(size_t)row * N + cn + j] = acc[i][j] + bias[cn + j];
    }
#endif
}

// ===========================================================================
// GEMM M128 x N256 (merged hi/lo, TR=128). Warp-specialized, NPIPE=2,
// 2 CTAs/SM (97KB smem, 256 TMEM cols/CTA). Stage = [A | B0 | B1].
// Halves A re-reads vs N128 -> QKV L2 traffic 402 -> 301 MB.
// ===========================================================================
__global__ __launch_bounds__(128, 2) void tc_gemm_n256(
    const __nv_bfloat16* __restrict__ A, const __nv_bfloat16* __restrict__ B,
    const float* __restrict__ bias, float* __restrict__ C,
    int M, int N, int K)
{
    extern __shared__ char smem[];
    const int tid = threadIdx.x;
    const int bm = blockIdx.y * 128;
    const int bn = blockIdx.x * 256;

#if TC_PATH
    const uint32_t smem_base = smem_u32(smem);
    const int wid  = tid >> 5;
    const int lane = tid & 31;

#define FULLB(b) (smem_base + 8  + 16 * (b))
#define EMPTB(b) (smem_base + 64 + 16 * (b))

    if (wid == 0) {
        TCGEN05_ALLOC(smem_base, 256);
        TCGEN05_RELINQUISH_ALLOC_PERMIT();
        if (lane == 0) {
#pragma unroll
            for (int b = 0; b < NP256; b++) {
                MBARRIER_INIT(FULLB(b), 1);
                MBARRIER_INIT(EMPTB(b), 1);
            }
        }
    }
    __syncthreads();
    uint32_t tmem;
    asm volatile("ld.shared.b32 %0, [%1];" : "=r"(tmem) : "r"(smem_base));

    const int nstage = K >> 5;
    const int nkblk  = K >> 5;

    if (tid == 32) {
        const size_t arow = (size_t)(bm >> 7) * nkblk;
        const size_t br0  = (size_t)((bn >> 7) + 0) * nkblk;
        const size_t br1  = (size_t)((bn >> 7) + 1) * nkblk;
        int eph[NP256] = {0, 0};
        int buf = 0;
        for (int s = 0; s < nstage; s++) {
            const uint32_t OFF = smem_base + 1024 + buf * STAGE256;
            if (s >= NP256) { MBARRIER_WAIT_PARITY(EMPTB(buf), eph[buf]); eph[buf] ^= 1; }
            MBARRIER_EXPECT_TX(FULLB(buf), STAGE256);
            BULK_G2S(OFF,         (const char*)A + ((arow + s) << 14), 16384, FULLB(buf));
            BULK_G2S(OFF + 16384, (const char*)B + ((br0  + s) << 14), 16384, FULLB(buf));
            BULK_G2S(OFF + 32768, (const char*)B + ((br1  + s) << 14), 16384, FULLB(buf));
            if (++buf == NP256) buf = 0;
        }
#pragma unroll
        for (int b = 0; b < NP256; b++)
            MBARRIER_WAIT_PARITY(EMPTB(b), eph[b]);
    }
    if (tid == 0) {
        int fph[NP256] = {0, 0};
        int buf = 0;
        for (int s = 0; s < nstage; s++) {
            const uint32_t OFF = smem_base + 1024 + buf * STAGE256;

            MBARRIER_WAIT_PARITY(FULLB(buf), fph[buf]); fph[buf] ^= 1;

            uint64_t ah = MAKE_SMEM_DESC_SW64(OFF);
            uint64_t al = MAKE_SMEM_DESC_SW64(OFF + 8192);
#pragma unroll
            for (int j = 0; j < 2; j++) {
                uint64_t bh = MAKE_SMEM_DESC_SW64(OFF + 16384 + j * 16384);
                uint64_t bl = MAKE_SMEM_DESC_SW64(OFF + 16384 + j * 16384 + 8192);
                const uint32_t dacc = tmem + j * 128;
#pragma unroll
                for (int kk = 0; kk < 2; kk++) {
                    uint32_t en = (s > 0 || kk > 0) ? 1u : 0u;
                    mma_f16_ss_cg1(dacc, ah + kk*2, bh + kk*2, GEMM_IDESC, en);
                    mma_f16_ss_cg1(dacc, ah + kk*2, bl + kk*2, GEMM_IDESC, 1u);
                    mma_f16_ss_cg1(dacc, al + kk*2, bh + kk*2, GEMM_IDESC, 1u);
                }
            }
            TCGEN05_COMMIT(EMPTB(buf));
            if (++buf == NP256) buf = 0;
        }
    }
    __syncthreads();
    TCGEN05_FENCE_AFTER();

    // Epilogue: 4 warps, each row writes 256 cols (two accumulators)
    {
        const int rowo = bm + wid * 32 + lane;
#pragma unroll
        for (int j = 0; j < 2; j++) {
            const uint32_t dacc = tmem + j * 128;
#pragma unroll
            for (int cb = 0; cb < 128; cb += 32) {
                uint32_t d[32];
                TCGEN05_LD_32X32B_X32(d, dacc + cb);
                TCGEN05_WAIT_LD();
                const int cno = bn + j * 128 + cb;
                float* crow = C + (size_t)rowo * N + cno;
#pragma unroll
                for (int g = 0; g < 8; g++) {
                    float4 bb = __ldg((const float4*)(bias + cno + g * 4));
                    float4 o;
                    o.x = __uint_as_float(d[g*4+0]) + bb.x;
                    o.y = __uint_as_float(d[g*4+1]) + bb.y;
                    o.z = __uint_as_float(d[g*4+2]) + bb.z;
                    o.w = __uint_as_float(d[g*4+3]) + bb.w;
                    *(float4*)(crow + g * 4) = o;
                }
            }
        }
    }
    __syncthreads();
    if (wid == 0) {
        TCGEN05_DEALLOC(tmem, 256);
    }
#undef FULLB
#undef EMPTB

#else
    // FFMA fallback: two sequential 128x128 subtiles
    float* As = (float*)smem;
    float* Bs = (float*)(smem + 4096);

    const int trow = tid >> 4;
    const int tcol = tid & 15;

    for (int nj = 0; nj < 2; nj++) {
        const int bnh = bn + nj * 128;
        float acc[16][8];
#pragma unroll
        for (int i = 0; i < 16; i++)
#pragma unroll
            for (int j = 0; j < 8; j++) acc[i][j] = 0.0f;

        for (int k0 = 0; k0 < K; k0 += 8) {
            for (int idx = tid; idx < 8 * 128; idx += 128) {
                int kk = idx >> 7, rr = idx & 127;
                As[kk * 128 + rr] =
                    ld_tiled(A, bm + rr, k0 + kk, K, 0) +
                    ld_tiled(A, bm + rr, k0 + kk, K, 1);
                Bs[kk * 128 + rr] =
                    ld_tiled(B, bnh + rr, k0 + kk, K, 0) +
                    ld_tiled(B, bnh + rr, k0 + kk, K, 1);
            }
            __syncthreads();
#pragma unroll
            for (int kk = 0; kk < 8; kk++) {
                float a[16], b[8];
#pragma unroll
                for (int e = 0; e < 16; e++) a[e] = As[kk * 128 + trow * 16 + e];
#pragma unroll
                for (int e = 0; e < 8; e++)  b[e] = Bs[kk * 128 + tcol * 8 + e];
#pragma unroll
                for (int i = 0; i < 16; i++)
#pragma unroll
                    for (int j = 0; j < 8; j++)
                        acc[i][j] += a[i] * b[j];
            }
            __syncthreads();
        }
        const int cn = bnh + tcol * 8;
#pragma unroll
        for (int i = 0; i < 16; i++) {
            const int row = bm + trow * 16 + i;
#pragma unroll
            for (int j = 0; j < 8; j++)
                C[(size_t)row * N + cn + j] = acc[i][j] + bias[cn + j];
        }
        __syncthreads();
    }
#endif
}

// ===========================================================================
// Band attention (R11 winner): one thread = one query, online softmax.
// Writes att in MERGED tiled+swizzled bf16 hi/lo (TR=128).
// ===========================================================================
#define ATT_PAD 68
#define ATT_SMEM (2 * 96 * ATT_PAD * 4)

__global__ __launch_bounds__(64) void band_attn_kernel(
    const float* __restrict__ qkv, const float* __restrict__ radius,
    __nv_bfloat16* __restrict__ att)
{
    extern __shared__ float sm[];
    float* sK = sm;
    float* sV = sm + 96 * ATT_PAD;

    const int tid = threadIdx.x;
    const int q0 = blockIdx.x * 64;
    const int h  = blockIdx.y;
    const int b  = blockIdx.z;

    float rr = 16.0f / (1.0f + expf(-radius[h]));
    if (rr < 1.0f) rr = 1.0f;
    const int R = (int)floorf(rr);

    const int klo = max(0, q0 - R);
    const int khi = min(SEQT - 1, q0 + 63 + R);
    const int Wt  = khi - klo + 1;

    const float* base = qkv + (size_t)b * SEQT * THREE_D;

    for (int i = tid; i < Wt * 16; i += 64) {
        int row = i >> 4;
        int c4  = (i & 15) * 4;
        const float* kr = base + (size_t)(klo + row) * THREE_D + DMODEL + h * HD + c4;
        *(float4*)&sK[row * ATT_PAD + c4] = __ldg((const float4*)kr);
        *(float4*)&sV[row * ATT_PAD + c4] = __ldg((const float4*)(kr + DMODEL));
    }

    const int q = q0 + tid;

    float qv[64];
    {
        const float* qrow = base + (size_t)q * THREE_D + h * HD;
#pragma unroll
        for (int g = 0; g < 16; g++) {
            float4 v = __ldg((const float4*)(qrow + g * 4));
            qv[g*4+0] = v.x; qv[g*4+1] = v.y; qv[g*4+2] = v.z; qv[g*4+3] = v.w;
        }
    }

    const int ks = max(0, q - R);
    const int ke = min(SEQT - 1, q + R);

    __syncthreads();

    float acc[64];
#pragma unroll
    for (int d = 0; d < 64; d++) acc[d] = 0.0f;
    float mrun = -3.402823466e38f;
    float ssum = 0.0f;

    for (int k = ks; k <= ke; k++) {
        const float* kr = &sK[(k - klo) * ATT_PAD];
        float s = 0.0f;
#pragma unroll
        for (int g = 0; g < 16; g++) {
            float4 kv = *(const float4*)(kr + g * 4);
            s += qv[g*4+0]*kv.x + qv[g*4+1]*kv.y + qv[g*4+2]*kv.z + qv[g*4+3]*kv.w;
        }
        s *= 0.125f;

        float mnew  = fmaxf(mrun, s);
        float scale = __expf(mrun - mnew);
        float e     = __expf(s - mnew);
        ssum = ssum * scale + e;

        const float* vr = &sV[(k - klo) * ATT_PAD];
#pragma unroll
        for (int g = 0; g < 16; g++) {
            float4 vv = *(const float4*)(vr + g * 4);
            acc[g*4+0] = acc[g*4+0] * scale + e * vv.x;
            acc[g*4+1] = acc[g*4+1] * scale + e * vv.y;
            acc[g*4+2] = acc[g*4+2] * scale + e * vv.z;
            acc[g*4+3] = acc[g*4+3] * scale + e * vv.w;
        }
        mrun = mnew;
    }

    const float inv = 1.0f / ssum;

    const int row = b * SEQT + q;
    const int rblk = row >> 7, rin = row & 127;
#pragma unroll
    for (int g = 0; g < 8; g++) {
        const int col8 = h * 8 + g;
        const int kblk = col8 >> 2, cc = col8 & 3;
        size_t tile = ((size_t)(rblk * 16 + kblk)) << 14;
        uint32_t bo = sw64((uint32_t)(rin * 64 + cc * 16));
        uint4 hi, lo;
        uint32_t* ph = (uint32_t*)&hi;
        uint32_t* pl = (uint32_t*)&lo;
#pragma unroll
        for (int p = 0; p < 4; p++) {
            float o0 = acc[g*8 + p*2]     * inv;
            float o1 = acc[g*8 + p*2 + 1] * inv;
            __nv_bfloat16 h0, l0, h1, l1;
            split_hilo(o0, h0, l0);
            split_hilo(o1, h1, l1);
            ph[p] = pack_bf16x2(h0, h1);
            pl[p] = pack_bf16x2(l0, l1);
        }
        *(uint4*)((char*)att + tile + bo)        = hi;
        *(uint4*)((char*)att + tile + 8192 + bo) = lo;
    }
}

// ---------------------------------------------------------------------------
extern "C" void kernel_launch(void* const* d_in, const int* in_sizes, int n_in,
                              void* d_out, int out_size)
{
    const float* x      = (const float*)d_in[0];
    const float* radius = (const float*)d_in[1];
    const float* w_in   = (const float*)d_in[2];
    const float* b_in   = (const float*)d_in[3];
    const float* w_out  = (const float*)d_in[4];
    const float* b_out  = (const float*)d_in[5];
    float* out = (float*)d_out;

    float *qkv;
    __nv_bfloat16 *xm, *wim, *wom, *attm;
    cudaGetSymbolAddress((void**)&qkv,  g_qkv);
    cudaGetSymbolAddress((void**)&xm,   g_x);
    cudaGetSymbolAddress((void**)&wim,  g_wi);
    cudaGetSymbolAddress((void**)&wom,  g_wo);
    cudaGetSymbolAddress((void**)&attm, g_att);

    cudaFuncSetAttribute(tc_gemm_128,
                         cudaFuncAttributeMaxDynamicSharedMemorySize, SMEM128);
    cudaFuncSetAttribute(tc_gemm_n256,
                         cudaFuncAttributeMaxDynamicSharedMemorySize, SMEM256);
    cudaFuncSetAttribute(band_attn_kernel,
                         cudaFuncAttributeMaxDynamicSharedMemorySize, ATT_SMEM);

    // 0) fp32 -> merged tiled+swizzled bf16 hi/lo (all TR=128)
    {
        int n8;
        n8 = (MROWS * DMODEL) / 8;
        cvt_tiled_kernel<<<(n8 + 255) / 256, 256>>>(x, xm, MROWS, DMODEL);
        n8 = (THREE_D * DMODEL) / 8;
        cvt_tiled_kernel<<<(n8 + 255) / 256, 256>>>(w_in, wim, THREE_D, DMODEL);
        n8 = (DMODEL * DMODEL) / 8;
        cvt_tiled_kernel<<<(n8 + 255) / 256, 256>>>(w_out, wom, DMODEL, DMODEL);
    }

    // 1) QKV projection: M128 x N256 tiles, grid (6, 64) = 384 CTAs
    {
        dim3 grid(THREE_D / 256, MROWS / 128);
        tc_gemm_n256<<<grid, 128, SMEM256>>>(
            xm, wim, b_in, qkv, MROWS, THREE_D, DMODEL);
    }

    // 2) Band attention -> att (merged tiled bf16 hi/lo)
    {
        dim3 grid(SEQT / 64, NHEAD, BATCH);
        band_attn_kernel<<<grid, 64, ATT_SMEM>>>(qkv, radius, attm);
    }

    // 3) Output projection: 128x128 tiles, grid (4, 64) = 256 CTAs
    {
        dim3 grid(DMODEL / 128, MROWS / 128);
        tc_gemm_128<<<grid, 128, SMEM128>>>(
            attm, wom, b_out, out, MROWS, DMODEL, DMODEL);
    }
}

// round 16
// speedup vs baseline: 1.1429x; 1.1429x over previous
#include <cuda_runtime.h>
#include <cuda_bf16.h>
#include <cstdint>

// Problem constants
#define BATCH 4
#define SEQT  2048
#define DMODEL 512
#define NHEAD 8
#define HD    64
#define THREE_D (3 * DMODEL)
#define MROWS (BATCH * SEQT)        // 8192

// Arch-feature dispatch: tcgen05/bulk-async only on *a targets.
#if !defined(__CUDA_ARCH__)
#  define TC_PATH 1
#elif defined(__CUDA_ARCH_HAS_FEATURE__) && \
      (__CUDA_ARCH_HAS_FEATURE__(SM103_ALL) || __CUDA_ARCH_HAS_FEATURE__(SM100_ALL))
#  define TC_PATH 1
#else
#  define TC_PATH 0
#endif

// ---------------------------------------------------------------------------
// MERGED tiled+swizzled bf16 hi/lo operand layout (SW64), TR=128:
//   tile t = (rblk * (K/32) + kblk) occupies 16 KB at t*16384:
//     [hi half: 8 KB][lo half: 8 KB]
//   within a half: row r, col c (bf16): bo = r*64 + c*2, bo ^= ((bo>>3)&0x30)
// ---------------------------------------------------------------------------

// Scratch (no cudaMalloc allowed)
__device__ float g_qkv[(size_t)MROWS * THREE_D];   // 48 MB fp32
__device__ alignas(128) __nv_bfloat16 g_x  [(size_t)MROWS   * DMODEL * 2];
__device__ alignas(128) __nv_bfloat16 g_wi [(size_t)THREE_D * DMODEL * 2];
__device__ alignas(128) __nv_bfloat16 g_wo [(size_t)DMODEL  * DMODEL * 2];
__device__ alignas(128) __nv_bfloat16 g_att[(size_t)MROWS   * DMODEL * 2];

// ===========================================================================
// Common helpers
// ===========================================================================
__device__ __forceinline__ uint32_t pack_bf16x2(__nv_bfloat16 a, __nv_bfloat16 b) {
    return (uint32_t)__bfloat16_as_ushort(a) |
           ((uint32_t)__bfloat16_as_ushort(b) << 16);
}

__device__ __forceinline__ void split_hilo(float v, __nv_bfloat16& h, __nv_bfloat16& l) {
    h = __float2bfloat16(v);
    l = __float2bfloat16(v - __bfloat162float(h));
}

__device__ __forceinline__ uint32_t sw64(uint32_t bo) {
    return bo ^ ((bo >> 3) & 0x30);
}

// merged-tiled element load (fallback path only), TR=128; half=0 hi, 1 lo
__device__ __forceinline__ float ld_tiled(
    const __nv_bfloat16* base, int row, int col, int Kdim, int half)
{
    int kblk = col >> 5, cin = col & 31;
    int rblk = row >> 7, rin = row & 127;
    size_t tile = ((size_t)(rblk * (Kdim >> 5) + kblk)) << 14;
    uint32_t bo = sw64((uint32_t)(rin * 64 + cin * 2)) + half * 8192;
    return __bfloat162float(*(const __nv_bfloat16*)((const char*)base + tile + bo));
}

// ===========================================================================
// ONE merged convert launch: fp32 row-major -> MERGED tiled bf16 hi/lo
// for all three operands (x, w_in, w_out). K is 512 for all, so kblk math
// is shared. Region boundaries in 8-elem granules.
// ===========================================================================
#define N8_X  ((MROWS   * DMODEL) / 8)    // 524288
#define N8_WI ((THREE_D * DMODEL) / 8)    //  98304
#define N8_WO ((DMODEL  * DMODEL) / 8)    //  32768
#define N8_TOTAL (N8_X + N8_WI + N8_WO)

__global__ __launch_bounds__(256) void cvt_all_kernel(
    const float* __restrict__ x, const float* __restrict__ wi,
    const float* __restrict__ wo,
    __nv_bfloat16* __restrict__ dx, __nv_bfloat16* __restrict__ dwi,
    __nv_bfloat16* __restrict__ dwo)
{
    int gi = blockIdx.x * blockDim.x + threadIdx.x;
    if (gi >= N8_TOTAL) return;

    const float* src;
    __nv_bfloat16* dst;
    int i;
    if (gi < N8_X)              { src = x;  dst = dx;  i = gi; }
    else if (gi < N8_X + N8_WI) { src = wi; dst = dwi; i = gi - N8_X; }
    else                        { src = wo; dst = dwo; i = gi - N8_X - N8_WI; }

    const int K8 = DMODEL >> 3;           // 64 granules per row
    int row = i / K8;
    int c8  = i - row * K8;

    float4 v0 = __ldg((const float4*)src + i * 2);
    float4 v1 = __ldg((const float4*)src + i * 2 + 1);

    __nv_bfloat16 h0,l0,h1,l1,h2,l2,h3,l3,h4,l4,h5,l5,h6,l6,h7,l7;
    split_hilo(v0.x,h0,l0); split_hilo(v0.y,h1,l1);
    split_hilo(v0.z,h2,l2); split_hilo(v0.w,h3,l3);
    split_hilo(v1.x,h4,l4); split_hilo(v1.y,h5,l5);
    split_hilo(v1.z,h6,l6); split_hilo(v1.w,h7,l7);
    uint4 hi, lo;
    hi.x = pack_bf16x2(h0,h1); hi.y = pack_bf16x2(h2,h3);
    hi.z = pack_bf16x2(h4,h5); hi.w = pack_bf16x2(h6,h7);
    lo.x = pack_bf16x2(l0,l1); lo.y = pack_bf16x2(l2,l3);
    lo.z = pack_bf16x2(l4,l5); lo.w = pack_bf16x2(l6,l7);

    int kblk = c8 >> 2, cc = c8 & 3;
    int rblk = row >> 7, rin = row & 127;
    size_t tile = ((size_t)(rblk * (DMODEL >> 5) + kblk)) << 14;
    uint32_t bo = sw64((uint32_t)(rin * 64 + cc * 16));
    *(uint4*)((char*)dst + tile + bo)        = hi;
    *(uint4*)((char*)dst + tile + 8192 + bo) = lo;
}

// ===========================================================================
// tcgen05 + bulk-async PTX helpers (feature-gated)
// ===========================================================================
#if TC_PATH
__device__ __forceinline__ uint32_t smem_u32(const void* p) {
    uint32_t a;
    asm("{ .reg .u64 t; cvta.to.shared.u64 t, %1; cvt.u32.u64 %0, t; }"
        : "=r"(a) : "l"(p));
    return a;
}

#define TCGEN05_ALLOC(smem_result_addr, nCols) \
    asm volatile( \
        "tcgen05.alloc.cta_group::1.sync.aligned.shared::cta.b32 [%0], %1;" \
        :: "r"((uint32_t)(smem_result_addr)), "r"((uint32_t)(nCols)) : "memory")

#define TCGEN05_DEALLOC(tmem_addr, nCols) \
    asm volatile( \
        "tcgen05.dealloc.cta_group::1.sync.aligned.b32 %0, %1;" \
        :: "r"(tmem_addr), "r"((uint32_t)(nCols)))

#define TCGEN05_RELINQUISH_ALLOC_PERMIT() \
    asm volatile("tcgen05.relinquish_alloc_permit.cta_group::1.sync.aligned;")

#define TCGEN05_COMMIT(mbar_smem_addr) \
    asm volatile( \
        "tcgen05.commit.cta_group::1.mbarrier::arrive::one.shared::cluster.b64 [%0];" \
        :: "r"((uint32_t)(mbar_smem_addr)) : "memory")

#define TCGEN05_FENCE_AFTER() \
    asm volatile("tcgen05.fence::after_thread_sync;" ::: "memory")

#define TCGEN05_WAIT_LD() \
    asm volatile("tcgen05.wait::ld.sync.aligned;" ::: "memory")

#define MBARRIER_INIT(mbar_smem_addr, count) \
    asm volatile( \
        "mbarrier.init.shared.b64 [%0], %1;" \
        :: "r"((uint32_t)(mbar_smem_addr)), "r"((uint32_t)(count)) : "memory")

#define MBARRIER_EXPECT_TX(mbar_smem_addr, tx_bytes) \
    asm volatile( \
        "mbarrier.arrive.expect_tx.shared.b64 _, [%0], %1;" \
        :: "r"((uint32_t)(mbar_smem_addr)), "r"((uint32_t)(tx_bytes)) : "memory")

#define MBARRIER_WAIT_PARITY(mbar_smem_addr, phase_parity) do { \
    uint32_t _mbar = (uint32_t)(mbar_smem_addr); \
    uint32_t _parity = (uint32_t)(phase_parity); \
    uint32_t _done; \
    asm volatile( \
        "{\n\t.reg .pred p;\n\t" \
        "mbarrier.try_wait.parity.acquire.cta.shared::cta.b64 p, [%1], %2;\n\t" \
        "selp.b32 %0, 1, 0, p;\n\t}" \
        : "=r"(_done) : "r"(_mbar), "r"(_parity) : "memory"); \
    if (!_done) { \
        asm volatile( \
            "{\n\t.reg .pred P1;\n\t" \
            "WAIT_LOOP_%=:\n\t" \
            "mbarrier.try_wait.parity.acquire.cta.shared::cta.b64 P1, [%0], %1, 0x989680;\n\t" \
            "@P1 bra.uni WAIT_DONE_%=;\n\t" \
            "bra.uni WAIT_LOOP_%=;\n\t" \
            "WAIT_DONE_%=:\n\t}" \
            :: "r"(_mbar), "r"(_parity) : "memory"); \
    } \
} while(0)

#define BULK_G2S(dst_smem, src_gmem, nbytes, mbar) \
    asm volatile( \
        "cp.async.bulk.shared::cluster.global.mbarrier::complete_tx::bytes " \
        "[%0], [%1], %2, [%3];" \
        :: "r"((uint32_t)(dst_smem)), "l"(src_gmem), "r"((uint32_t)(nbytes)), \
           "r"((uint32_t)(mbar)) : "memory")

#define TCGEN05_LD_32X32B_X32(r, tmem_addr) \
    asm volatile( \
        "tcgen05.ld.sync.aligned.32x32b.x32.b32 " \
        "{%0, %1, %2, %3, %4, %5, %6, %7, " \
        " %8, %9, %10, %11, %12, %13, %14, %15, " \
        " %16, %17, %18, %19, %20, %21, %22, %23, " \
        " %24, %25, %26, %27, %28, %29, %30, %31}, [%32];" \
        : "=r"((r)[0]),  "=r"((r)[1]),  "=r"((r)[2]),  "=r"((r)[3]), \
          "=r"((r)[4]),  "=r"((r)[5]),  "=r"((r)[6]),  "=r"((r)[7]), \
          "=r"((r)[8]),  "=r"((r)[9]),  "=r"((r)[10]), "=r"((r)[11]), \
          "=r"((r)[12]), "=r"((r)[13]), "=r"((r)[14]), "=r"((r)[15]), \
          "=r"((r)[16]), "=r"((r)[17]), "=r"((r)[18]), "=r"((r)[19]), \
          "=r"((r)[20]), "=r"((r)[21]), "=r"((r)[22]), "=r"((r)[23]), \
          "=r"((r)[24]), "=r"((r)[25]), "=r"((r)[26]), "=r"((r)[27]), \
          "=r"((r)[28]), "=r"((r)[29]), "=r"((r)[30]), "=r"((r)[31]) \
        : "r"(tmem_addr))

// SW64 descriptor: layout=4, version=1, SBO=32 (512B atom), LBO=1 (16B)
static constexpr uint64_t SMEM_DESC_BASE_SW64 =
    (uint64_t(4)  << 61) | (uint64_t(1) << 46) |
    (uint64_t(32) << 32) | (uint64_t(1) << 16);
#define MAKE_SMEM_DESC_SW64(base_addr) \
    (SMEM_DESC_BASE_SW64 | ((uint64_t)((base_addr) >> 4) & 0x3FFF))

__device__ __forceinline__ void mma_f16_ss_cg1(
    uint32_t d_tmem, uint64_t a_desc, uint64_t b_desc,
    uint32_t idesc, uint32_t enable)
{
    asm volatile(
        "{\n\t.reg .pred p;\n\t"
        "setp.ne.u32 p, %4, 0;\n\t"
        "tcgen05.mma.cta_group::1.kind::f16 [%0], %1, %2, %3, "
        "{%5, %5, %5, %5}, p;\n\t}"
        :: "r"(d_tmem), "l"(a_desc), "l"(b_desc), "r"(idesc),
           "r"(enable), "r"(0u)
        : "memory");
}

#define GEMM_IDESC ((1u<<4)|(1u<<7)|(1u<<10)|(16u<<17)|(8u<<24))  // M128 N128 bf16 f32acc
#endif // TC_PATH

// 128x128 kernel: NPIPE=2 x 32KB stage = 66KB -> 3 CTAs/SM (R14 winner)
#define STAGE_BYTES 32768
#define NPIPE 2
#define GEMM_SMEM_TOTAL (1024 + NPIPE * STAGE_BYTES)

// ===========================================================================
// GEMM 128x128 (merged hi/lo, TR=128). Warp-specialized, NPIPE=2, 3 CTAs/SM.
// ===========================================================================
__global__ __launch_bounds__(128, 3) void tc_gemm_128(
    const __nv_bfloat16* __restrict__ A, const __nv_bfloat16* __restrict__ B,
    const float* __restrict__ bias, float* __restrict__ C,
    int M, int N, int K)
{
    extern __shared__ char smem[];
    const int tid = threadIdx.x;
    const int bm = blockIdx.y * 128;
    const int bn = blockIdx.x * 128;

#if TC_PATH
    const uint32_t smem_base = smem_u32(smem);
    const int wid  = tid >> 5;
    const int lane = tid & 31;

#define FULLB(b) (smem_base + 8  + 16 * (b))
#define EMPTB(b) (smem_base + 64 + 16 * (b))

    if (wid == 0) {
        TCGEN05_ALLOC(smem_base, 128);
        TCGEN05_RELINQUISH_ALLOC_PERMIT();
        if (lane == 0) {
#pragma unroll
            for (int b = 0; b < NPIPE; b++) {
                MBARRIER_INIT(FULLB(b), 1);
                MBARRIER_INIT(EMPTB(b), 1);
            }
        }
    }
    __syncthreads();
    uint32_t tmem;
    asm volatile("ld.shared.b32 %0, [%1];" : "=r"(tmem) : "r"(smem_base));

    const int nstage = K >> 5;
    const int nkblk  = K >> 5;

    if (tid == 32) {
        const size_t arow = (size_t)(bm >> 7) * nkblk;
        const size_t brow = (size_t)(bn >> 7) * nkblk;
        int eph[NPIPE] = {0, 0};
        int buf = 0;
        for (int s = 0; s < nstage; s++) {
            const uint32_t OFF = smem_base + 1024 + buf * STAGE_BYTES;
            if (s >= NPIPE) { MBARRIER_WAIT_PARITY(EMPTB(buf), eph[buf]); eph[buf] ^= 1; }
            MBARRIER_EXPECT_TX(FULLB(buf), STAGE_BYTES);
            BULK_G2S(OFF,         (const char*)A + ((arow + s) << 14), 16384, FULLB(buf));
            BULK_G2S(OFF + 16384, (const char*)B + ((brow + s) << 14), 16384, FULLB(buf));
            if (++buf == NPIPE) buf = 0;
        }
#pragma unroll
        for (int b = 0; b < NPIPE; b++)
            MBARRIER_WAIT_PARITY(EMPTB(b), eph[b]);
    }
    if (tid == 0) {
        int fph[NPIPE] = {0, 0};
        int buf = 0;
        for (int s = 0; s < nstage; s++) {
            const uint32_t OFF = smem_base + 1024 + buf * STAGE_BYTES;

            MBARRIER_WAIT_PARITY(FULLB(buf), fph[buf]); fph[buf] ^= 1;

            uint64_t ah = MAKE_SMEM_DESC_SW64(OFF);
            uint64_t al = MAKE_SMEM_DESC_SW64(OFF + 8192);
            uint64_t bh = MAKE_SMEM_DESC_SW64(OFF + 16384);
            uint64_t bl = MAKE_SMEM_DESC_SW64(OFF + 24576);
#pragma unroll
            for (int kk = 0; kk < 2; kk++) {
                uint32_t en = (s > 0 || kk > 0) ? 1u : 0u;
                mma_f16_ss_cg1(tmem, ah + kk*2, bh + kk*2, GEMM_IDESC, en);
                mma_f16_ss_cg1(tmem, ah + kk*2, bl + kk*2, GEMM_IDESC, 1u);
                mma_f16_ss_cg1(tmem, al + kk*2, bh + kk*2, GEMM_IDESC, 1u);
            }
            TCGEN05_COMMIT(EMPTB(buf));
            if (++buf == NPIPE) buf = 0;
        }
    }
    __syncthreads();
    TCGEN05_FENCE_AFTER();

    {
        const int rowo = bm + wid * 32 + lane;
#pragma unroll
        for (int cb = 0; cb < 128; cb += 32) {
            uint32_t d[32];
            TCGEN05_LD_32X32B_X32(d, tmem + cb);
            TCGEN05_WAIT_LD();
            float* crow = C + (size_t)rowo * N + bn + cb;
#pragma unroll
            for (int g = 0; g < 8; g++) {
                float4 bb = __ldg((const float4*)(bias + bn + cb + g * 4));
                float4 o;
                o.x = __uint_as_float(d[g*4+0]) + bb.x;
                o.y = __uint_as_float(d[g*4+1]) + bb.y;
                o.z = __uint_as_float(d[g*4+2]) + bb.z;
                o.w = __uint_as_float(d[g*4+3]) + bb.w;
                *(float4*)(crow + g * 4) = o;
            }
        }
    }
    __syncthreads();
    if (wid == 0) {
        TCGEN05_DEALLOC(tmem, 128);
    }
#undef FULLB
#undef EMPTB

#else
    // FFMA fallback 128x128 (merged tiled loads)
    float* As = (float*)smem;
    float* Bs = (float*)(smem + 4096);

    const int trow = tid >> 4;
    const int tcol = tid & 15;
    float acc[16][8];
#pragma unroll
    for (int i = 0; i < 16; i++)
#pragma unroll
        for (int j = 0; j < 8; j++) acc[i][j] = 0.0f;

    for (int k0 = 0; k0 < K; k0 += 8) {
        for (int idx = tid; idx < 8 * 128; idx += 128) {
            int kk = idx >> 7, rr = idx & 127;
            As[kk * 128 + rr] =
                ld_tiled(A, bm + rr, k0 + kk, K, 0) +
                ld_tiled(A, bm + rr, k0 + kk, K, 1);
            Bs[kk * 128 + rr] =
                ld_tiled(B, bn + rr, k0 + kk, K, 0) +
                ld_tiled(B, bn + rr, k0 + kk, K, 1);
        }
        __syncthreads();
#pragma unroll
        for (int kk = 0; kk < 8; kk++) {
            float a[16], b[8];
#pragma unroll
            for (int e = 0; e < 16; e++) a[e] = As[kk * 128 + trow * 16 + e];
#pragma unroll
            for (int e = 0; e < 8; e++)  b[e] = Bs[kk * 128 + tcol * 8 + e];
#pragma unroll
            for (int i = 0; i < 16; i++)
#pragma unroll
                for (int j = 0; j < 8; j++)
                    acc[i][j] += a[i] * b[j];
        }
        __syncthreads();
    }
    const int cn = bn + tcol * 8;
#pragma unroll
    for (int i = 0; i < 16; i++) {
        const int row = bm + trow * 16 + i;
#pragma unroll
        for (int j = 0; j < 8; j++)
            C[(size_t)row * N + cn + j] = acc[i][j] + bias[cn + j];
    }
#endif
}

// ===========================================================================
// Band attention (R11 winner): one thread = one query, online softmax.
// Writes att in MERGED tiled+swizzled bf16 hi/lo (TR=128).
// ===========================================================================
#define ATT_PAD 68
#define ATT_SMEM (2 * 96 * ATT_PAD * 4)

__global__ __launch_bounds__(64) void band_attn_kernel(
    const float* __restrict__ qkv, const float* __restrict__ radius,
    __nv_bfloat16* __restrict__ att)
{
    extern __shared__ float sm[];
    float* sK = sm;
    float* sV = sm + 96 * ATT_PAD;

    const int tid = threadIdx.x;
    const int q0 = blockIdx.x * 64;
    const int h  = blockIdx.y;
    const int b  = blockIdx.z;

    float rr = 16.0f / (1.0f + expf(-radius[h]));
    if (rr < 1.0f) rr = 1.0f;
    const int R = (int)floorf(rr);

    const int klo = max(0, q0 - R);
    const int khi = min(SEQT - 1, q0 + 63 + R);
    const int Wt  = khi - klo + 1;

    const float* base = qkv + (size_t)b * SEQT * THREE_D;

    for (int i = tid; i < Wt * 16; i += 64) {
        int row = i >> 4;
        int c4  = (i & 15) * 4;
        const float* kr = base + (size_t)(klo + row) * THREE_D + DMODEL + h * HD + c4;
        *(float4*)&sK[row * ATT_PAD + c4] = __ldg((const float4*)kr);
        *(float4*)&sV[row * ATT_PAD + c4] = __ldg((const float4*)(kr + DMODEL));
    }

    const int q = q0 + tid;

    float qv[64];
    {
        const float* qrow = base + (size_t)q * THREE_D + h * HD;
#pragma unroll
        for (int g = 0; g < 16; g++) {
            float4 v = __ldg((const float4*)(qrow + g * 4));
            qv[g*4+0] = v.x; qv[g*4+1] = v.y; qv[g*4+2] = v.z; qv[g*4+3] = v.w;
        }
    }

    const int ks = max(0, q - R);
    const int ke = min(SEQT - 1, q + R);

    __syncthreads();

    float acc[64];
#pragma unroll
    for (int d = 0; d < 64; d++) acc[d] = 0.0f;
    float mrun = -3.402823466e38f;
    float ssum = 0.0f;

    for (int k = ks; k <= ke; k++) {
        const float* kr = &sK[(k - klo) * ATT_PAD];
        float s = 0.0f;
#pragma unroll
        for (int g = 0; g < 16; g++) {
            float4 kv = *(const float4*)(kr + g * 4);
            s += qv[g*4+0]*kv.x + qv[g*4+1]*kv.y + qv[g*4+2]*kv.z + qv[g*4+3]*kv.w;
        }
        s *= 0.125f;

        float mnew  = fmaxf(mrun, s);
        float scale = __expf(mrun - mnew);
        float e     = __expf(s - mnew);
        ssum = ssum * scale + e;

        const float* vr = &sV[(k - klo) * ATT_PAD];
#pragma unroll
        for (int g = 0; g < 16; g++) {
            float4 vv = *(const float4*)(vr + g * 4);
            acc[g*4+0] = acc[g*4+0] * scale + e * vv.x;
            acc[g*4+1] = acc[g*4+1] * scale + e * vv.y;
            acc[g*4+2] = acc[g*4+2] * scale + e * vv.z;
            acc[g*4+3] = acc[g*4+3] * scale + e * vv.w;
        }
        mrun = mnew;
    }

    const float inv = 1.0f / ssum;

    const int row = b * SEQT + q;
    const int rblk = row >> 7, rin = row & 127;
#pragma unroll
    for (int g = 0; g < 8; g++) {
        const int col8 = h * 8 + g;
        const int kblk = col8 >> 2, cc = col8 & 3;
        size_t tile = ((size_t)(rblk * 16 + kblk)) << 14;
        uint32_t bo = sw64((uint32_t)(rin * 64 + cc * 16));
        uint4 hi, lo;
        uint32_t* ph = (uint32_t*)&hi;
        uint32_t* pl = (uint32_t*)&lo;
#pragma unroll
        for (int p = 0; p < 4; p++) {
            float o0 = acc[g*8 + p*2]     * inv;
            float o1 = acc[g*8 + p*2 + 1] * inv;
            __nv_bfloat16 h0, l0, h1, l1;
            split_hilo(o0, h0, l0);
            split_hilo(o1, h1, l1);
            ph[p] = pack_bf16x2(h0, h1);
            pl[p] = pack_bf16x2(l0, l1);
        }
        *(uint4*)((char*)att + tile + bo)        = hi;
        *(uint4*)((char*)att + tile + 8192 + bo) = lo;
    }
}

// ---------------------------------------------------------------------------
extern "C" void kernel_launch(void* const* d_in, const int* in_sizes, int n_in,
                              void* d_out, int out_size)
{
    const float* x      = (const float*)d_in[0];
    const float* radius = (const float*)d_in[1];
    const float* w_in   = (const float*)d_in[2];
    const float* b_in   = (const float*)d_in[3];
    const float* w_out  = (const float*)d_in[4];
    const float* b_out  = (const float*)d_in[5];
    float* out = (float*)d_out;

    float *qkv;
    __nv_bfloat16 *xm, *wim, *wom, *attm;
    cudaGetSymbolAddress((void**)&qkv,  g_qkv);
    cudaGetSymbolAddress((void**)&xm,   g_x);
    cudaGetSymbolAddress((void**)&wim,  g_wi);
    cudaGetSymbolAddress((void**)&wom,  g_wo);
    cudaGetSymbolAddress((void**)&attm, g_att);

    cudaFuncSetAttribute(tc_gemm_128,
                         cudaFuncAttributeMaxDynamicSharedMemorySize,
                         GEMM_SMEM_TOTAL);
    cudaFuncSetAttribute(band_attn_kernel,
                         cudaFuncAttributeMaxDynamicSharedMemorySize, ATT_SMEM);

    // 0) ONE merged convert launch for x, w_in, w_out
    {
        int blocks = (N8_TOTAL + 255) / 256;
        cvt_all_kernel<<<blocks, 256>>>(x, w_in, w_out, xm, wim, wom);
    }

    // 1) QKV projection: 128x128 tiles, grid (12, 64) = 768 CTAs, 3 CTAs/SM
    {
        dim3 grid(THREE_D / 128, MROWS / 128);
        tc_gemm_128<<<grid, 128, GEMM_SMEM_TOTAL>>>(
            xm, wim, b_in, qkv, MROWS, THREE_D, DMODEL);
    }

    // 2) Band attention -> att (merged tiled bf16 hi/lo)
    {
        dim3 grid(SEQT / 64, NHEAD, BATCH);
        band_attn_kernel<<<grid, 64, ATT_SMEM>>>(qkv, radius, attm);
    }

    // 3) Output projection: 128x128 tiles, grid (4, 64) = 256 CTAs
    {
        dim3 grid(DMODEL / 128, MROWS / 128);
        tc_gemm_128<<<grid, 128, GEMM_SMEM_TOTAL>>>(
            attm, wom, b_out, out, MROWS, DMODEL, DMODEL);
    }
}

// round 17
// speedup vs baseline: 1.2418x; 1.0866x over previous
#include <cuda_runtime.h>
#include <cuda_fp16.h>
#include <cstdint>

// Problem constants
#define BATCH 4
#define SEQT  2048
#define DMODEL 512
#define NHEAD 8
#define HD    64
#define THREE_D (3 * DMODEL)
#define MROWS (BATCH * SEQT)        // 8192

// Arch-feature dispatch: tcgen05/bulk-async only on *a targets.
#if !defined(__CUDA_ARCH__)
#  define TC_PATH 1
#elif defined(__CUDA_ARCH_HAS_FEATURE__) && \
      (__CUDA_ARCH_HAS_FEATURE__(SM103_ALL) || __CUDA_ARCH_HAS_FEATURE__(SM100_ALL))
#  define TC_PATH 1
#else
#  define TC_PATH 0
#endif

// ---------------------------------------------------------------------------
// fp16 operand layouts (SW64, TR=128):
//   A-side (x, att): MERGED hi/lo — tile t occupies 16 KB at t<<14:
//     [hi half: 8 KB][lo half: 8 KB]
//   B-side (weights): HI ONLY — tile t occupies 8 KB at t<<13.
//   within a half: row r, col c (fp16): bo = r*64 + c*2, bo ^= ((bo>>3)&0x30)
// 2-pass MMA: D = Ah*Bh + Al*Bh = (A)*Bh; dropped A*Bl ~ 2^-11 rel.
// ---------------------------------------------------------------------------

// Scratch (no cudaMalloc allowed)
__device__ float g_qkv[(size_t)MROWS * THREE_D];   // 48 MB fp32
__device__ alignas(128) __half g_x  [(size_t)MROWS   * DMODEL * 2];  // hi/lo
__device__ alignas(128) __half g_wi [(size_t)THREE_D * DMODEL];      // hi
__device__ alignas(128) __half g_wo [(size_t)DMODEL  * DMODEL];      // hi
__device__ alignas(128) __half g_att[(size_t)MROWS   * DMODEL * 2];  // hi/lo

// ===========================================================================
// Common helpers
// ===========================================================================
__device__ __forceinline__ uint32_t pack_h2(__half a, __half b) {
    return (uint32_t)__half_as_ushort(a) |
           ((uint32_t)__half_as_ushort(b) << 16);
}

__device__ __forceinline__ void split_hilo(float v, __half& h, __half& l) {
    h = __float2half_rn(v);
    l = __float2half_rn(v - __half2float(h));
}

__device__ __forceinline__ uint32_t sw64(uint32_t bo) {
    return bo ^ ((bo >> 3) & 0x30);
}

// tiled loads (fallback path only), TR=128
__device__ __forceinline__ float ld_tiled_a(   // merged hi/lo: full value
    const __half* base, int row, int col, int Kdim)
{
    int kblk = col >> 5, cin = col & 31;
    int rblk = row >> 7, rin = row & 127;
    size_t tile = ((size_t)(rblk * (Kdim >> 5) + kblk)) << 14;
    uint32_t bo = sw64((uint32_t)(rin * 64 + cin * 2));
    float h = __half2float(*(const __half*)((const char*)base + tile + bo));
    float l = __half2float(*(const __half*)((const char*)base + tile + 8192 + bo));
    return h + l;
}
__device__ __forceinline__ float ld_tiled_b(   // hi only
    const __half* base, int row, int col, int Kdim)
{
    int kblk = col >> 5, cin = col & 31;
    int rblk = row >> 7, rin = row & 127;
    size_t tile = ((size_t)(rblk * (Kdim >> 5) + kblk)) << 13;
    uint32_t bo = sw64((uint32_t)(rin * 64 + cin * 2));
    return __half2float(*(const __half*)((const char*)base + tile + bo));
}

// ===========================================================================
// ONE merged convert launch: fp32 row-major -> tiled fp16.
//   x -> merged hi/lo (A layout); wi, wo -> hi only (B layout).
// ===========================================================================
#define N8_X  ((MROWS   * DMODEL) / 8)    // 524288
#define N8_WI ((THREE_D * DMODEL) / 8)    //  98304
#define N8_WO ((DMODEL  * DMODEL) / 8)    //  32768
#define N8_TOTAL (N8_X + N8_WI + N8_WO)

__global__ __launch_bounds__(256) void cvt_all_kernel(
    const float* __restrict__ x, const float* __restrict__ wi,
    const float* __restrict__ wo,
    __half* __restrict__ dx, __half* __restrict__ dwi,
    __half* __restrict__ dwo)
{
    int gi = blockIdx.x * blockDim.x + threadIdx.x;
    if (gi >= N8_TOTAL) return;

    const float* src;
    __half* dst;
    int i;
    int hilo;   // 1 = A layout (hi/lo), 0 = B layout (hi only)
    if (gi < N8_X)              { src = x;  dst = dx;  i = gi;               hilo = 1; }
    else if (gi < N8_X + N8_WI) { src = wi; dst = dwi; i = gi - N8_X;        hilo = 0; }
    else                        { src = wo; dst = dwo; i = gi - N8_X - N8_WI; hilo = 0; }

    const int K8 = DMODEL >> 3;           // 64 granules per row
    int row = i / K8;
    int c8  = i - row * K8;

    float4 v0 = __ldg((const float4*)src + i * 2);
    float4 v1 = __ldg((const float4*)src + i * 2 + 1);

    __half h0,l0,h1,l1,h2,l2,h3,l3,h4,l4,h5,l5,h6,l6,h7,l7;
    split_hilo(v0.x,h0,l0); split_hilo(v0.y,h1,l1);
    split_hilo(v0.z,h2,l2); split_hilo(v0.w,h3,l3);
    split_hilo(v1.x,h4,l4); split_hilo(v1.y,h5,l5);
    split_hilo(v1.z,h6,l6); split_hilo(v1.w,h7,l7);
    uint4 hi;
    hi.x = pack_h2(h0,h1); hi.y = pack_h2(h2,h3);
    hi.z = pack_h2(h4,h5); hi.w = pack_h2(h6,h7);

    int kblk = c8 >> 2, cc = c8 & 3;
    int rblk = row >> 7, rin = row & 127;
    uint32_t bo = sw64((uint32_t)(rin * 64 + cc * 16));

    if (hilo) {
        uint4 lo;
        lo.x = pack_h2(l0,l1); lo.y = pack_h2(l2,l3);
        lo.z = pack_h2(l4,l5); lo.w = pack_h2(l6,l7);
        size_t tile = ((size_t)(rblk * (DMODEL >> 5) + kblk)) << 14;
        *(uint4*)((char*)dst + tile + bo)        = hi;
        *(uint4*)((char*)dst + tile + 8192 + bo) = lo;
    } else {
        size_t tile = ((size_t)(rblk * (DMODEL >> 5) + kblk)) << 13;
        *(uint4*)((char*)dst + tile + bo) = hi;
    }
}

// ===========================================================================
// tcgen05 + bulk-async PTX helpers (feature-gated)
// ===========================================================================
#if TC_PATH
__device__ __forceinline__ uint32_t smem_u32(const void* p) {
    uint32_t a;
    asm("{ .reg .u64 t; cvta.to.shared.u64 t, %1; cvt.u32.u64 %0, t; }"
        : "=r"(a) : "l"(p));
    return a;
}

#define TCGEN05_ALLOC(smem_result_addr, nCols) \
    asm volatile( \
        "tcgen05.alloc.cta_group::1.sync.aligned.shared::cta.b32 [%0], %1;" \
        :: "r"((uint32_t)(smem_result_addr)), "r"((uint32_t)(nCols)) : "memory")

#define TCGEN05_DEALLOC(tmem_addr, nCols) \
    asm volatile( \
        "tcgen05.dealloc.cta_group::1.sync.aligned.b32 %0, %1;" \
        :: "r"(tmem_addr), "r"((uint32_t)(nCols)))

#define TCGEN05_RELINQUISH_ALLOC_PERMIT() \
    asm volatile("tcgen05.relinquish_alloc_permit.cta_group::1.sync.aligned;")

#define TCGEN05_COMMIT(mbar_smem_addr) \
    asm volatile( \
        "tcgen05.commit.cta_group::1.mbarrier::arrive::one.shared::cluster.b64 [%0];" \
        :: "r"((uint32_t)(mbar_smem_addr)) : "memory")

#define TCGEN05_FENCE_AFTER() \
    asm volatile("tcgen05.fence::after_thread_sync;" ::: "memory")

#define TCGEN05_WAIT_LD() \
    asm volatile("tcgen05.wait::ld.sync.aligned;" ::: "memory")

#define MBARRIER_INIT(mbar_smem_addr, count) \
    asm volatile( \
        "mbarrier.init.shared.b64 [%0], %1;" \
        :: "r"((uint32_t)(mbar_smem_addr)), "r"((uint32_t)(count)) : "memory")

#define MBARRIER_EXPECT_TX(mbar_smem_addr, tx_bytes) \
    asm volatile( \
        "mbarrier.arrive.expect_tx.shared.b64 _, [%0], %1;" \
        :: "r"((uint32_t)(mbar_smem_addr)), "r"((uint32_t)(tx_bytes)) : "memory")

#define MBARRIER_WAIT_PARITY(mbar_smem_addr, phase_parity) do { \
    uint32_t _mbar = (uint32_t)(mbar_smem_addr); \
    uint32_t _parity = (uint32_t)(phase_parity); \
    uint32_t _done; \
    asm volatile( \
        "{\n\t.reg .pred p;\n\t" \
        "mbarrier.try_wait.parity.acquire.cta.shared::cta.b64 p, [%1], %2;\n\t" \
        "selp.b32 %0, 1, 0, p;\n\t}" \
        : "=r"(_done) : "r"(_mbar), "r"(_parity) : "memory"); \
    if (!_done) { \
        asm volatile( \
            "{\n\t.reg .pred P1;\n\t" \
            "WAIT_LOOP_%=:\n\t" \
            "mbarrier.try_wait.parity.acquire.cta.shared::cta.b64 P1, [%0], %1, 0x989680;\n\t" \
            "@P1 bra.uni WAIT_DONE_%=;\n\t" \
            "bra.uni WAIT_LOOP_%=;\n\t" \
            "WAIT_DONE_%=:\n\t}" \
            :: "r"(_mbar), "r"(_parity) : "memory"); \
    } \
} while(0)

#define BULK_G2S(dst_smem, src_gmem, nbytes, mbar) \
    asm volatile( \
        "cp.async.bulk.shared::cluster.global.mbarrier::complete_tx::bytes " \
        "[%0], [%1], %2, [%3];" \
        :: "r"((uint32_t)(dst_smem)), "l"(src_gmem), "r"((uint32_t)(nbytes)), \
           "r"((uint32_t)(mbar)) : "memory")

#define TCGEN05_LD_32X32B_X32(r, tmem_addr) \
    asm volatile( \
        "tcgen05.ld.sync.aligned.32x32b.x32.b32 " \
        "{%0, %1, %2, %3, %4, %5, %6, %7, " \
        " %8, %9, %10, %11, %12, %13, %14, %15, " \
        " %16, %17, %18, %19, %20, %21, %22, %23, " \
        " %24, %25, %26, %27, %28, %29, %30, %31}, [%32];" \
        : "=r"((r)[0]),  "=r"((r)[1]),  "=r"((r)[2]),  "=r"((r)[3]), \
          "=r"((r)[4]),  "=r"((r)[5]),  "=r"((r)[6]),  "=r"((r)[7]), \
          "=r"((r)[8]),  "=r"((r)[9]),  "=r"((r)[10]), "=r"((r)[11]), \
          "=r"((r)[12]), "=r"((r)[13]), "=r"((r)[14]), "=r"((r)[15]), \
          "=r"((r)[16]), "=r"((r)[17]), "=r"((r)[18]), "=r"((r)[19]), \
          "=r"((r)[20]), "=r"((r)[21]), "=r"((r)[22]), "=r"((r)[23]), \
          "=r"((r)[24]), "=r"((r)[25]), "=r"((r)[26]), "=r"((r)[27]), \
          "=r"((r)[28]), "=r"((r)[29]), "=r"((r)[30]), "=r"((r)[31]) \
        : "r"(tmem_addr))

// SW64 descriptor: layout=4, version=1, SBO=32 (512B atom), LBO=1 (16B)
static constexpr uint64_t SMEM_DESC_BASE_SW64 =
    (uint64_t(4)  << 61) | (uint64_t(1) << 46) |
    (uint64_t(32) << 32) | (uint64_t(1) << 16);
#define MAKE_SMEM_DESC_SW64(base_addr) \
    (SMEM_DESC_BASE_SW64 | ((uint64_t)((base_addr) >> 4) & 0x3FFF))

__device__ __forceinline__ void mma_f16_ss_cg1(
    uint32_t d_tmem, uint64_t a_desc, uint64_t b_desc,
    uint32_t idesc, uint32_t enable)
{
    asm volatile(
        "{\n\t.reg .pred p;\n\t"
        "setp.ne.u32 p, %4, 0;\n\t"
        "tcgen05.mma.cta_group::1.kind::f16 [%0], %1, %2, %3, "
        "{%5, %5, %5, %5}, p;\n\t}"
        :: "r"(d_tmem), "l"(a_desc), "l"(b_desc), "r"(idesc),
           "r"(enable), "r"(0u)
        : "memory");
}

// fp16 inputs (atype=btype=0), fp32 acc, M=128, N=128
#define GEMM_IDESC ((1u<<4)|(16u<<17)|(8u<<24))
#endif // TC_PATH

// Stage = Ah(8K) + Al(8K) + Bh(8K) = 24KB. NPIPE=3 -> 74.75KB -> 3 CTAs/SM.
#define STAGE_BYTES 24576
#define NPIPE 3
#define GEMM_SMEM_TOTAL (1024 + NPIPE * STAGE_BYTES)

// ===========================================================================
// GEMM 128x128, fp16 2-pass: D = Ah*Bh + Al*Bh. Warp-specialized, NPIPE=3,
// 3 CTAs/SM (9 buffered stages per SM cover the commit->refill chain).
// ===========================================================================
__global__ __launch_bounds__(128, 3) void tc_gemm_128(
    const __half* __restrict__ A, const __half* __restrict__ B,
    const float* __restrict__ bias, float* __restrict__ C,
    int M, int N, int K)
{
    extern __shared__ char smem[];
    const int tid = threadIdx.x;
    const int bm = blockIdx.y * 128;
    const int bn = blockIdx.x * 128;

#if TC_PATH
    const uint32_t smem_base = smem_u32(smem);
    const int wid  = tid >> 5;
    const int lane = tid & 31;

#define FULLB(b) (smem_base + 8   + 16 * (b))
#define EMPTB(b) (smem_base + 64  + 16 * (b))

    if (wid == 0) {
        TCGEN05_ALLOC(smem_base, 128);
        TCGEN05_RELINQUISH_ALLOC_PERMIT();
        if (lane == 0) {
#pragma unroll
            for (int b = 0; b < NPIPE; b++) {
                MBARRIER_INIT(FULLB(b), 1);
                MBARRIER_INIT(EMPTB(b), 1);
            }
        }
    }
    __syncthreads();
    uint32_t tmem;
    asm volatile("ld.shared.b32 %0, [%1];" : "=r"(tmem) : "r"(smem_base));

    const int nstage = K >> 5;
    const int nkblk  = K >> 5;

    if (tid == 32) {
        const size_t arow = (size_t)(bm >> 7) * nkblk;
        const size_t brow = (size_t)(bn >> 7) * nkblk;
        int eph[NPIPE] = {0, 0, 0};
        int buf = 0;
        for (int s = 0; s < nstage; s++) {
            const uint32_t OFF = smem_base + 1024 + buf * STAGE_BYTES;
            if (s >= NPIPE) { MBARRIER_WAIT_PARITY(EMPTB(buf), eph[buf]); eph[buf] ^= 1; }
            MBARRIER_EXPECT_TX(FULLB(buf), STAGE_BYTES);
            BULK_G2S(OFF,         (const char*)A + ((arow + s) << 14), 16384, FULLB(buf));
            BULK_G2S(OFF + 16384, (const char*)B + ((brow + s) << 13),  8192, FULLB(buf));
            if (++buf == NPIPE) buf = 0;
        }
#pragma unroll
        for (int b = 0; b < NPIPE; b++)
            MBARRIER_WAIT_PARITY(EMPTB(b), eph[b]);
    }
    if (tid == 0) {
        int fph[NPIPE] = {0, 0, 0};
        int buf = 0;
        for (int s = 0; s < nstage; s++) {
            const uint32_t OFF = smem_base + 1024 + buf * STAGE_BYTES;

            MBARRIER_WAIT_PARITY(FULLB(buf), fph[buf]); fph[buf] ^= 1;

            uint64_t ah = MAKE_SMEM_DESC_SW64(OFF);
            uint64_t al = MAKE_SMEM_DESC_SW64(OFF + 8192);
            uint64_t bh = MAKE_SMEM_DESC_SW64(OFF + 16384);
#pragma unroll
            for (int kk = 0; kk < 2; kk++) {
                uint32_t en = (s > 0 || kk > 0) ? 1u : 0u;
                mma_f16_ss_cg1(tmem, ah + kk*2, bh + kk*2, GEMM_IDESC, en);
                mma_f16_ss_cg1(tmem, al + kk*2, bh + kk*2, GEMM_IDESC, 1u);
            }
            TCGEN05_COMMIT(EMPTB(buf));
            if (++buf == NPIPE) buf = 0;
        }
    }
    __syncthreads();
    TCGEN05_FENCE_AFTER();

    {
        const int rowo = bm + wid * 32 + lane;
#pragma unroll
        for (int cb = 0; cb < 128; cb += 32) {
            uint32_t d[32];
            TCGEN05_LD_32X32B_X32(d, tmem + cb);
            TCGEN05_WAIT_LD();
            float* crow = C + (size_t)rowo * N + bn + cb;
#pragma unroll
            for (int g = 0; g < 8; g++) {
                float4 bb = __ldg((const float4*)(bias + bn + cb + g * 4));
                float4 o;
                o.x = __uint_as_float(d[g*4+0]) + bb.x;
                o.y = __uint_as_float(d[g*4+1]) + bb.y;
                o.z = __uint_as_float(d[g*4+2]) + bb.z;
                o.w = __uint_as_float(d[g*4+3]) + bb.w;
                *(float4*)(crow + g * 4) = o;
            }
        }
    }
    __syncthreads();
    if (wid == 0) {
        TCGEN05_DEALLOC(tmem, 128);
    }
#undef FULLB
#undef EMPTB

#else
    // FFMA fallback 128x128
    float* As = (float*)smem;
    float* Bs = (float*)(smem + 4096);

    const int trow = tid >> 4;
    const int tcol = tid & 15;
    float acc[16][8];
#pragma unroll
    for (int i = 0; i < 16; i++)
#pragma unroll
        for (int j = 0; j < 8; j++) acc[i][j] = 0.0f;

    for (int k0 = 0; k0 < K; k0 += 8) {
        for (int idx = tid; idx < 8 * 128; idx += 128) {
            int kk = idx >> 7, rr = idx & 127;
            As[kk * 128 + rr] = ld_tiled_a(A, bm + rr, k0 + kk, K);
            Bs[kk * 128 + rr] = ld_tiled_b(B, bn + rr, k0 + kk, K);
        }
        __syncthreads();
#pragma unroll
        for (int kk = 0; kk < 8; kk++) {
            float a[16], b[8];
#pragma unroll
            for (int e = 0; e < 16; e++) a[e] = As[kk * 128 + trow * 16 + e];
#pragma unroll
            for (int e = 0; e < 8; e++)  b[e] = Bs[kk * 128 + tcol * 8 + e];
#pragma unroll
            for (int i = 0; i < 16; i++)
#pragma unroll
                for (int j = 0; j < 8; j++)
                    acc[i][j] += a[i] * b[j];
        }
        __syncthreads();
    }
    const int cn = bn + tcol * 8;
#pragma unroll
    for (int i = 0; i < 16; i++) {
        const int row = bm + trow * 16 + i;
#pragma unroll
        for (int j = 0; j < 8; j++)
            C[(size_t)row * N + cn + j] = acc[i][j] + bias[cn + j];
    }
#endif
}

// ===========================================================================
// Band attention (R11 winner): one thread = one query, online softmax.
// Writes att as MERGED tiled fp16 hi/lo (A layout, TR=128).
// ===========================================================================
#define ATT_PAD 68
#define ATT_SMEM (2 * 96 * ATT_PAD * 4)

__global__ __launch_bounds__(64) void band_attn_kernel(
    const float* __restrict__ qkv, const float* __restrict__ radius,
    __half* __restrict__ att)
{
    extern __shared__ float sm[];
    float* sK = sm;
    float* sV = sm + 96 * ATT_PAD;

    const int tid = threadIdx.x;
    const int q0 = blockIdx.x * 64;
    const int h  = blockIdx.y;
    const int b  = blockIdx.z;

    float rr = 16.0f / (1.0f + expf(-radius[h]));
    if (rr < 1.0f) rr = 1.0f;
    const int R = (int)floorf(rr);

    const int klo = max(0, q0 - R);
    const int khi = min(SEQT - 1, q0 + 63 + R);
    const int Wt  = khi - klo + 1;

    const float* base = qkv + (size_t)b * SEQT * THREE_D;

    for (int i = tid; i < Wt * 16; i += 64) {
        int row = i >> 4;
        int c4  = (i & 15) * 4;
        const float* kr = base + (size_t)(klo + row) * THREE_D + DMODEL + h * HD + c4;
        *(float4*)&sK[row * ATT_PAD + c4] = __ldg((const float4*)kr);
        *(float4*)&sV[row * ATT_PAD + c4] = __ldg((const float4*)(kr + DMODEL));
    }

    const int q = q0 + tid;

    float qv[64];
    {
        const float* qrow = base + (size_t)q * THREE_D + h * HD;
#pragma unroll
        for (int g = 0; g < 16; g++) {
            float4 v = __ldg((const float4*)(qrow + g * 4));
            qv[g*4+0] = v.x; qv[g*4+1] = v.y; qv[g*4+2] = v.z; qv[g*4+3] = v.w;
        }
    }

    const int ks = max(0, q - R);
    const int ke = min(SEQT - 1, q + R);

    __syncthreads();

    float acc[64];
#pragma unroll
    for (int d = 0; d < 64; d++) acc[d] = 0.0f;
    float mrun = -3.402823466e38f;
    float ssum = 0.0f;

    for (int k = ks; k <= ke; k++) {
        const float* kr = &sK[(k - klo) * ATT_PAD];
        float s = 0.0f;
#pragma unroll
        for (int g = 0; g < 16; g++) {
            float4 kv = *(const float4*)(kr + g * 4);
            s += qv[g*4+0]*kv.x + qv[g*4+1]*kv.y + qv[g*4+2]*kv.z + qv[g*4+3]*kv.w;
        }
        s *= 0.125f;

        float mnew  = fmaxf(mrun, s);
        float scale = __expf(mrun - mnew);
        float e     = __expf(s - mnew);
        ssum = ssum * scale + e;

        const float* vr = &sV[(k - klo) * ATT_PAD];
#pragma unroll
        for (int g = 0; g < 16; g++) {
            float4 vv = *(const float4*)(vr + g * 4);
            acc[g*4+0] = acc[g*4+0] * scale + e * vv.x;
            acc[g*4+1] = acc[g*4+1] * scale + e * vv.y;
            acc[g*4+2] = acc[g*4+2] * scale + e * vv.z;
            acc[g*4+3] = acc[g*4+3] * scale + e * vv.w;
        }
        mrun = mnew;
    }

    const float inv = 1.0f / ssum;

    // write att row as MERGED tiled fp16 hi/lo (TR=128, 16 kblks/row-tile)
    const int row = b * SEQT + q;
    const int rblk = row >> 7, rin = row & 127;
#pragma unroll
    for (int g = 0; g < 8; g++) {
        const int col8 = h * 8 + g;
        const int kblk = col8 >> 2, cc = col8 & 3;
        size_t tile = ((size_t)(rblk * 16 + kblk)) << 14;
        uint32_t bo = sw64((uint32_t)(rin * 64 + cc * 16));
        uint4 hi, lo;
        uint32_t* ph = (uint32_t*)&hi;
        uint32_t* pl = (uint32_t*)&lo;
#pragma unroll
        for (int p = 0; p < 4; p++) {
            float o0 = acc[g*8 + p*2]     * inv;
            float o1 = acc[g*8 + p*2 + 1] * inv;
            __half h0, l0, h1, l1;
            split_hilo(o0, h0, l0);
            split_hilo(o1, h1, l1);
            ph[p] = pack_h2(h0, h1);
            pl[p] = pack_h2(l0, l1);
        }
        *(uint4*)((char*)att + tile + bo)        = hi;
        *(uint4*)((char*)att + tile + 8192 + bo) = lo;
    }
}

// ---------------------------------------------------------------------------
extern "C" void kernel_launch(void* const* d_in, const int* in_sizes, int n_in,
                              void* d_out, int out_size)
{
    const float* x      = (const float*)d_in[0];
    const float* radius = (const float*)d_in[1];
    const float* w_in   = (const float*)d_in[2];
    const float* b_in   = (const float*)d_in[3];
    const float* w_out  = (const float*)d_in[4];
    const float* b_out  = (const float*)d_in[5];
    float* out = (float*)d_out;

    float *qkv;
    __half *xm, *wim, *wom, *attm;
    cudaGetSymbolAddress((void**)&qkv,  g_qkv);
    cudaGetSymbolAddress((void**)&xm,   g_x);
    cudaGetSymbolAddress((void**)&wim,  g_wi);
    cudaGetSymbolAddress((void**)&wom,  g_wo);
    cudaGetSymbolAddress((void**)&attm, g_att);

    cudaFuncSetAttribute(tc_gemm_128,
                         cudaFuncAttributeMaxDynamicSharedMemorySize,
                         GEMM_SMEM_TOTAL);
    cudaFuncSetAttribute(band_attn_kernel,
                         cudaFuncAttributeMaxDynamicSharedMemorySize, ATT_SMEM);

    // 0) ONE merged convert launch for x (hi/lo), w_in (hi), w_out (hi)
    {
        int blocks = (N8_TOTAL + 255) / 256;
        cvt_all_kernel<<<blocks, 256>>>(x, w_in, w_out, xm, wim, wom);
    }

    // 1) QKV projection: 128x128 tiles, grid (12, 64) = 768 CTAs, 3 CTAs/SM
    {
        dim3 grid(THREE_D / 128, MROWS / 128);
        tc_gemm_128<<<grid, 128, GEMM_SMEM_TOTAL>>>(
            xm, wim, b_in, qkv, MROWS, THREE_D, DMODEL);
    }

    // 2) Band attention -> att (merged tiled fp16 hi/lo)
    {
        dim3 grid(SEQT / 64, NHEAD, BATCH);
        band_attn_kernel<<<grid, 64, ATT_SMEM>>>(qkv, radius, attm);
    }

    // 3) Output projection: 128x128 tiles, grid (4, 64) = 256 CTAs
    {
        dim3 grid(DMODEL / 128, MROWS / 128);
        tc_gemm_128<<<grid, 128, GEMM_SMEM_TOTAL>>>(
            attm, wom, b_out, out, MROWS, DMODEL, DMODEL);
    }
}